// round 15
// baseline (speedup 1.0000x reference)
#include <cuda_runtime.h>
#include <cuda_fp16.h>
#include <cuda_bf16.h>
#include <cstdint>

// ---------------------------------------------------------------------------
// SparseAttention: B=1, S=4096, D=1024, H=16, HD=64, BLOCK=128, C=32
// Round 15: attn with 64-row CTAs (128 thr, 4 warps, 4 CTAs/SM), diag-half
// work elimination, degree-4 exp poly. fp16 GEMMs unchanged from round 13.
// ---------------------------------------------------------------------------

#define S_LEN 4096
#define D_DIM 1024
#define N_HEADS 16
#define HEAD_DIM 64

__device__ __half g_qh[S_LEN * D_DIM];
__device__ __half g_kh[S_LEN * D_DIM];
__device__ __half g_vh[S_LEN * D_DIM];
__device__ __half g_ctxh[S_LEN * D_DIM];
__device__ __half g_xh[S_LEN * D_DIM];
__device__ __half g_wh[4 * D_DIM * D_DIM];   // W^T, [n][k], fp16

// ---------------------------------------------------------------------------
// helpers
// ---------------------------------------------------------------------------
__device__ __forceinline__ void mma_f16(float* c, const uint32_t* a, const uint32_t* b) {
    asm volatile(
        "mma.sync.aligned.m16n8k16.row.col.f32.f16.f16.f32 "
        "{%0,%1,%2,%3}, {%4,%5,%6,%7}, {%8,%9}, {%0,%1,%2,%3};"
        : "+f"(c[0]), "+f"(c[1]), "+f"(c[2]), "+f"(c[3])
        : "r"(a[0]), "r"(a[1]), "r"(a[2]), "r"(a[3]),
          "r"(b[0]), "r"(b[1]));
}

__device__ __forceinline__ void ldmx4t(uint32_t& r0, uint32_t& r1,
                                       uint32_t& r2, uint32_t& r3, uint32_t saddr) {
    asm volatile(
        "ldmatrix.sync.aligned.m8n8.x4.trans.shared.b16 {%0,%1,%2,%3}, [%4];"
        : "=r"(r0), "=r"(r1), "=r"(r2), "=r"(r3) : "r"(saddr));
}

// Fast e^x for x <= ~7 (handles -1e30 -> ~0). Degree-4 2^f poly,
// max rel err ~3e-5 (well under fp16 P storage rounding). No MUFU.
__device__ __forceinline__ float fexp(float x) {
    float y = fmaxf(x * 1.44269504089f, -125.0f);
    float z = y + 12582912.0f;              // 1.5*2^23 magic
    float nf = z - 12582912.0f;
    float f = y - nf;                        // f in [-0.5, 0.5]
    float p = 9.6181291e-3f;
    p = fmaf(p, f, 5.5504109e-2f);
    p = fmaf(p, f, 2.4022651e-1f);
    p = fmaf(p, f, 6.9314718e-1f);
    p = fmaf(p, f, 1.0f);
    int n = __float_as_int(z) - 0x4B400000;
    return __int_as_float(__float_as_int(p) + (n << 23));
}

__device__ __forceinline__ void cp16h(__half* smem_dst, const __half* gmem_src) {
    uint32_t s = (uint32_t)__cvta_generic_to_shared(smem_dst);
    asm volatile("cp.async.cg.shared.global [%0], [%1], 16;\n" :: "r"(s), "l"(gmem_src));
}
#define CP_COMMIT() asm volatile("cp.async.commit_group;\n" ::: "memory")
#define CP_WAIT1()  asm volatile("cp.async.wait_group 1;\n" ::: "memory")
#define CP_WAIT0()  asm volatile("cp.async.wait_group 0;\n" ::: "memory")

// ---------------------------------------------------------------------------
// Conversions: x -> fp16; W[k][n] -> W^T[n][k] fp16
// ---------------------------------------------------------------------------
__global__ void conv_x(const float4* __restrict__ x, uint2* __restrict__ xh) {
    const int i = blockIdx.x * blockDim.x + threadIdx.x;
    float4 v = x[i];
    __half2 lo = __floats2half2_rn(v.x, v.y);
    __half2 hi = __floats2half2_rn(v.z, v.w);
    uint2 o;
    o.x = *(uint32_t*)&lo;
    o.y = *(uint32_t*)&hi;
    xh[i] = o;
}

__global__ void conv_w(
    const float* __restrict__ W0, const float* __restrict__ W1,
    const float* __restrict__ W2, const float* __restrict__ W3,
    __half* __restrict__ out)
{
    __shared__ float tile[32][33];
    const int z = blockIdx.z;
    const float* src = (z == 0) ? W0 : (z == 1) ? W1 : (z == 2) ? W2 : W3;
    __half* dst = out + (size_t)z * D_DIM * D_DIM;
    const int bx = blockIdx.x * 32, by = blockIdx.y * 32;
    const int tx = threadIdx.x, ty = threadIdx.y;
#pragma unroll
    for (int i = 0; i < 4; i++)
        tile[ty + 8 * i][tx] = src[(size_t)(by + ty + 8 * i) * D_DIM + bx + tx];
    __syncthreads();
#pragma unroll
    for (int i = 0; i < 4; i++)
        dst[(size_t)(bx + ty + 8 * i) * D_DIM + by + tx] =
            __float2half_rn(tile[tx][ty + 8 * i]);
}

// ---------------------------------------------------------------------------
// fp16 GEMM (unchanged from round 13): C = (A @ B^T + bias) * scale.
// ---------------------------------------------------------------------------
#define HS 40
#define TILE_HG (128 * HS)
#define H_STAGE (2 * TILE_HG)
#define GEMM_SMEM_BYTES (3 * H_STAGE * 2)

__device__ __forceinline__ void gemm_load_tile_h(
    __half* As, __half* Bs, const __half* A, const __half* B,
    int m0, int n0, int k0, int tid)
{
#pragma unroll
    for (int rep = 0; rep < 4; rep++) {
        int idx = tid + 128 * rep;
        int row = idx >> 2;
        int c   = idx & 3;
        cp16h(As + row * HS + c * 8,
              A + (size_t)(m0 + row) * D_DIM + k0 + c * 8);
    }
#pragma unroll
    for (int rep = 0; rep < 4; rep++) {
        int idx = tid + 128 * rep;
        int row = idx >> 2;
        int c   = idx & 3;
        cp16h(Bs + row * HS + c * 8,
              B + (size_t)(n0 + row) * D_DIM + k0 + c * 8);
    }
}

template<int OUT_HALF>
__device__ __forceinline__ void gemm_body_h(
    const __half* __restrict__ A, const __half* __restrict__ B,
    const float* __restrict__ bias, void* __restrict__ Cout,
    float scale, __half* smh)
{
    __half* AsBuf[3] = { smh, smh + H_STAGE, smh + 2 * H_STAGE };
    __half* BsBuf[3] = { smh + TILE_HG, smh + H_STAGE + TILE_HG,
                         smh + 2 * H_STAGE + TILE_HG };

    const int tid = threadIdx.x;
    const int wid = tid >> 5;
    const int lane = tid & 31;
    const int g  = lane >> 2;
    const int t4 = lane & 3;
    const int warp_m = wid >> 1;
    const int warp_n = wid & 1;
    const int m0 = blockIdx.y * 128;
    const int n0 = blockIdx.x * 128;

    float acc[4][8][4];
#pragma unroll
    for (int mi = 0; mi < 4; mi++)
#pragma unroll
        for (int ni = 0; ni < 8; ni++)
#pragma unroll
            for (int r = 0; r < 4; r++) acc[mi][ni][r] = 0.0f;

    const int niter = D_DIM / 32;

    gemm_load_tile_h(AsBuf[0], BsBuf[0], A, B, m0, n0, 0, tid);
    CP_COMMIT();
    gemm_load_tile_h(AsBuf[1], BsBuf[1], A, B, m0, n0, 32, tid);
    CP_COMMIT();

    for (int it = 0; it < niter; it++) {
        const int s = it % 3;
        if (it == niter - 1) { CP_WAIT0(); } else { CP_WAIT1(); }
        __syncthreads();
        if (it + 2 < niter) {
            gemm_load_tile_h(AsBuf[(it + 2) % 3], BsBuf[(it + 2) % 3],
                             A, B, m0, n0, (it + 2) * 32, tid);
            CP_COMMIT();
        }

        const __half* aBase = AsBuf[s] + (warp_m * 64) * HS;
        const __half* bBase = BsBuf[s] + (warp_n * 64) * HS;

#pragma unroll
        for (int step = 0; step < 2; step++) {
            const int kh = step * 16 + 2 * t4;
            uint32_t af[4][4];
#pragma unroll
            for (int mi = 0; mi < 4; mi++) {
                int r0 = mi * 16 + g;
                af[mi][0] = *(const uint32_t*)(aBase + (r0)     * HS + kh);
                af[mi][1] = *(const uint32_t*)(aBase + (r0 + 8) * HS + kh);
                af[mi][2] = *(const uint32_t*)(aBase + (r0)     * HS + kh + 8);
                af[mi][3] = *(const uint32_t*)(aBase + (r0 + 8) * HS + kh + 8);
            }
            uint32_t bf[8][2];
#pragma unroll
            for (int ni = 0; ni < 8; ni++) {
                bf[ni][0] = *(const uint32_t*)(bBase + (ni * 8 + g) * HS + kh);
                bf[ni][1] = *(const uint32_t*)(bBase + (ni * 8 + g) * HS + kh + 8);
            }
#pragma unroll
            for (int mi = 0; mi < 4; mi++)
#pragma unroll
                for (int ni = 0; ni < 8; ni++)
                    mma_f16(acc[mi][ni], af[mi], bf[ni]);
        }
    }

#pragma unroll
    for (int mi = 0; mi < 4; mi++) {
        int row = m0 + warp_m * 64 + mi * 16 + g;
#pragma unroll
        for (int ni = 0; ni < 8; ni++) {
            int col = n0 + warp_n * 64 + ni * 8 + 2 * t4;
            float b0 = bias[col], b1 = bias[col + 1];
            float o0 = (acc[mi][ni][0] + b0) * scale;
            float o1 = (acc[mi][ni][1] + b1) * scale;
            float o2 = (acc[mi][ni][2] + b0) * scale;
            float o3 = (acc[mi][ni][3] + b1) * scale;
            if (OUT_HALF) {
                __half* C = (__half*)Cout;
                __half2 h0 = __floats2half2_rn(o0, o1);
                __half2 h1 = __floats2half2_rn(o2, o3);
                *(__half2*)(C + (size_t)row * D_DIM + col)       = h0;
                *(__half2*)(C + (size_t)(row + 8) * D_DIM + col) = h1;
            } else {
                float* C = (float*)Cout;
                C[(size_t)row * D_DIM + col]           = o0;
                C[(size_t)row * D_DIM + col + 1]       = o1;
                C[(size_t)(row + 8) * D_DIM + col]     = o2;
                C[(size_t)(row + 8) * D_DIM + col + 1] = o3;
            }
        }
    }
}

__global__ __launch_bounds__(128, 2) void sgemm_qkv(
    const __half* __restrict__ xh, const __half* __restrict__ wh,
    const float* __restrict__ bq, const float* __restrict__ bk,
    const float* __restrict__ bv,
    __half* __restrict__ q, __half* __restrict__ k, __half* __restrict__ v)
{
    extern __shared__ __half smh[];
    const int z = blockIdx.z;
    const __half* W = wh + (size_t)z * D_DIM * D_DIM;
    const float* b = (z == 0) ? bq : (z == 1) ? bk : bv;
    __half* C      = (z == 0) ? q  : (z == 1) ? k  : v;
    const float sc = (z == 0) ? 0.125f : 1.0f;
    gemm_body_h<1>(xh, W, b, C, sc, smh);
}

__global__ __launch_bounds__(128, 2) void sgemm_proj(
    const __half* __restrict__ A, const __half* __restrict__ B,
    const float* __restrict__ bias, float* __restrict__ C)
{
    extern __shared__ __half smh[];
    gemm_body_h<0>(A, B, bias, C, 1.0f, smh);
}

// ---------------------------------------------------------------------------
// Sparse flash attention: 64 q-rows per CTA (128 threads, 4 warps),
// 64-key tiles, 4 CTAs/SM. Diagonal split by q-half: half=0 handles one
// causal tile; half=1 one full + one causal tile.
// ---------------------------------------------------------------------------
__device__ __forceinline__ int gather_key(int gk) {
    int j = gk / 33;
    int r = gk - j * 33;
    return j * 128 + (r == 0 ? 0 : 95 + r);
}

#define TSH 72                       // halves per tile row (64 + 8 pad)
#define T_TILE_H (64 * TSH)          // halves per K or V tile
#define ATTN_SMEM_HALVES (4 * T_TILE_H + 64 * TSH)   // 23040 (45KB)
#define BIG_NEG (-1e30f)

__global__ __launch_bounds__(128, 4) void attn_kernel(
    const __half* __restrict__ Q, const __half* __restrict__ K,
    const __half* __restrict__ V, __half* __restrict__ ctxh)
{
    extern __shared__ __half smh[];
    __half* KsBuf[2] = { smh, smh + T_TILE_H };
    __half* VsBuf[2] = { smh + 2 * T_TILE_H, smh + 3 * T_TILE_H };
    __half* Ps = smh + 4 * T_TILE_H;   // [64][72]

    const int qb   = 31 - (blockIdx.x >> 1);   // big blocks first
    const int qhalf = blockIdx.x & 1;
    const int h  = blockIdx.y;
    const int tid = threadIdx.x;
    const int wid = tid >> 5;          // 0..3
    const int lane = tid & 31;
    const int g  = lane >> 2;
    const int t4 = lane & 3;

    const int nG = 33 * qb;
    const int nT = (nG + 63) >> 6;
    const int nTot = nT + 1 + qhalf;   // half=0: one causal diag; half=1: full + causal
    const int key_lane = tid >> 1;     // 0..63
    const int c2b      = tid & 1;      // 0..1

    // ---- Q fragments (global rows qb*128 + qhalf*64 + wid*16 ...) ----
    const __half* Qb = Q + (size_t)(qb * 128 + qhalf * 64 + wid * 16) * D_DIM + h * HEAD_DIM;
    uint32_t qa[4][4];
#pragma unroll
    for (int ks = 0; ks < 4; ks++) {
        int kh = ks * 16 + 2 * t4;
        qa[ks][0] = *(const uint32_t*)(Qb + (size_t)(g)     * D_DIM + kh);
        qa[ks][1] = *(const uint32_t*)(Qb + (size_t)(g + 8) * D_DIM + kh);
        qa[ks][2] = *(const uint32_t*)(Qb + (size_t)(g)     * D_DIM + kh + 8);
        qa[ks][3] = *(const uint32_t*)(Qb + (size_t)(g + 8) * D_DIM + kh + 8);
    }

    auto load_tile = [&](int t, int buf) {
        int gk;
        if (t >= nT) gk = qb * 128 + (t - nT) * 64 + key_lane;
        else {
            int gg = t * 64 + key_lane;
            gk = (gg < nG) ? gather_key(gg) : 0;
        }
        const __half* Krow = K + (size_t)gk * D_DIM + h * HEAD_DIM;
        const __half* Vrow = V + (size_t)gk * D_DIM + h * HEAD_DIM;
        __half* kd = KsBuf[buf] + key_lane * TSH;
        __half* vd = VsBuf[buf] + key_lane * TSH;
#pragma unroll
        for (int rep = 0; rep < 4; rep++) {
            int c = c2b * 4 + rep;            // 0..7 (8 halves each)
            cp16h(kd + c * 8, Krow + c * 8);
            cp16h(vd + c * 8, Vrow + c * 8);
        }
    };

    float lrow[2] = { 0.0f, 0.0f };
    float Oacc[8][4];
#pragma unroll
    for (int ni = 0; ni < 8; ni++)
#pragma unroll
        for (int r = 0; r < 4; r++) Oacc[ni][r] = 0.0f;

    load_tile(0, 0);
    CP_COMMIT();

    for (int t = 0; t < nTot; t++) {
        CP_WAIT0();
        __syncthreads();
        if (t + 1 < nTot) {
            load_tile(t + 1, (t + 1) & 1);
            CP_COMMIT();
        }
        const __half* Kb = KsBuf[t & 1];
        const __half* Vb = VsBuf[t & 1];

        // ---- S = Q K^T (16 x 64 per warp, fp16 MMA) ----
        float sacc[8][4];
#pragma unroll
        for (int ni = 0; ni < 8; ni++)
#pragma unroll
            for (int r = 0; r < 4; r++) sacc[ni][r] = 0.0f;

#pragma unroll
        for (int ks = 0; ks < 4; ks++) {
            const int kh = ks * 16 + 2 * t4;
#pragma unroll
            for (int ni = 0; ni < 8; ni++) {
                uint32_t b[2];
                b[0] = *(const uint32_t*)(Kb + (ni * 8 + g) * TSH + kh);
                b[1] = *(const uint32_t*)(Kb + (ni * 8 + g) * TSH + kh + 8);
                mma_f16(sacc[ni], qa[ks], b);
            }
        }

        // ---- mask: last tile is causal; gathered tail needs bounds ----
        const int r0 = wid * 16 + g;       // local row 0..63
        const int r1 = r0 + 8;
        if (t == nTot - 1) {
#pragma unroll
            for (int ni = 0; ni < 8; ni++) {
                int c0 = ni * 8 + 2 * t4;  // local key 0..63
                if (c0     > r0) sacc[ni][0] = BIG_NEG;
                if (c0 + 1 > r0) sacc[ni][1] = BIG_NEG;
                if (c0     > r1) sacc[ni][2] = BIG_NEG;
                if (c0 + 1 > r1) sacc[ni][3] = BIG_NEG;
            }
        } else if (t < nT && t * 64 + 64 > nG) {
            const int base = t * 64;
#pragma unroll
            for (int ni = 0; ni < 8; ni++) {
                int c0 = base + ni * 8 + 2 * t4;
                if (c0     >= nG) { sacc[ni][0] = BIG_NEG; sacc[ni][2] = BIG_NEG; }
                if (c0 + 1 >= nG) { sacc[ni][1] = BIG_NEG; sacc[ni][3] = BIG_NEG; }
            }
        }

        // ---- p = exp(s), partial l, store P fp16 ----
#pragma unroll
        for (int ni = 0; ni < 8; ni++) {
            float p0 = fexp(sacc[ni][0]);
            float p1 = fexp(sacc[ni][1]);
            float p2 = fexp(sacc[ni][2]);
            float p3 = fexp(sacc[ni][3]);
            lrow[0] += p0 + p1;
            lrow[1] += p2 + p3;
            int c = ni * 8 + 2 * t4;
            __half2 w0 = __floats2half2_rn(p0, p1);
            __half2 w1 = __floats2half2_rn(p2, p3);
            *(__half2*)(Ps + r0 * TSH + c) = w0;
            *(__half2*)(Ps + r1 * TSH + c) = w1;
        }
        __syncwarp();

        // ---- O += P @ V (V B-frags via ldmatrix.trans) ----
        const __half* pB = Ps + (wid * 16) * TSH;
#pragma unroll
        for (int ks = 0; ks < 4; ks++) {
            const int kh = ks * 16 + 2 * t4;
            uint32_t a[4];
            a[0] = *(const uint32_t*)(pB + (g)     * TSH + kh);
            a[1] = *(const uint32_t*)(pB + (g + 8) * TSH + kh);
            a[2] = *(const uint32_t*)(pB + (g)     * TSH + kh + 8);
            a[3] = *(const uint32_t*)(pB + (g + 8) * TSH + kh + 8);

            uint32_t bf[8][2];
#pragma unroll
            for (int np = 0; np < 4; np++) {
                int m = lane >> 3;
                int key = ks * 16 + (lane & 7) + 8 * (m & 1);
                int dcol = (2 * np + (m >> 1)) * 8;
                uint32_t saddr = (uint32_t)__cvta_generic_to_shared(
                    Vb + key * TSH + dcol);
                ldmx4t(bf[2 * np][0], bf[2 * np][1],
                       bf[2 * np + 1][0], bf[2 * np + 1][1], saddr);
            }
#pragma unroll
            for (int ni = 0; ni < 8; ni++)
                mma_f16(Oacc[ni], a, bf[ni]);
        }
    }

    // ---- final l reduction, epilogue (ctx fp16) ----
    lrow[0] += __shfl_xor_sync(0xffffffffu, lrow[0], 1);
    lrow[0] += __shfl_xor_sync(0xffffffffu, lrow[0], 2);
    lrow[1] += __shfl_xor_sync(0xffffffffu, lrow[1], 1);
    lrow[1] += __shfl_xor_sync(0xffffffffu, lrow[1], 2);

    const float inv0 = 1.0f / lrow[0];
    const float inv1 = 1.0f / lrow[1];
    const int gr0 = qb * 128 + qhalf * 64 + wid * 16 + g;
    const int gr1 = gr0 + 8;
#pragma unroll
    for (int ni = 0; ni < 8; ni++) {
        int c = h * HEAD_DIM + ni * 8 + 2 * t4;
        __half2 h0 = __floats2half2_rn(Oacc[ni][0] * inv0, Oacc[ni][1] * inv0);
        __half2 h1 = __floats2half2_rn(Oacc[ni][2] * inv1, Oacc[ni][3] * inv1);
        *(__half2*)(ctxh + (size_t)gr0 * D_DIM + c) = h0;
        *(__half2*)(ctxh + (size_t)gr1 * D_DIM + c) = h1;
    }
}

// ---------------------------------------------------------------------------
extern "C" void kernel_launch(void* const* d_in, const int* in_sizes, int n_in,
                              void* d_out, int out_size)
{
    const float* x  = (const float*)d_in[0];
    const float* Wq = (const float*)d_in[1];
    const float* bq = (const float*)d_in[2];
    const float* Wk = (const float*)d_in[3];
    const float* bk = (const float*)d_in[4];
    const float* Wv = (const float*)d_in[5];
    const float* bv = (const float*)d_in[6];
    const float* Wo = (const float*)d_in[7];
    const float* bo = (const float*)d_in[8];
    float* out = (float*)d_out;

    __half *qh, *kh, *vh, *ctxh, *xh, *wh;
    cudaGetSymbolAddress((void**)&qh,   g_qh);
    cudaGetSymbolAddress((void**)&kh,   g_kh);
    cudaGetSymbolAddress((void**)&vh,   g_vh);
    cudaGetSymbolAddress((void**)&ctxh, g_ctxh);
    cudaGetSymbolAddress((void**)&xh,   g_xh);
    cudaGetSymbolAddress((void**)&wh,   g_wh);

    const int attn_smem = ATTN_SMEM_HALVES * 2;   // 46080 bytes
    cudaFuncSetAttribute(attn_kernel, cudaFuncAttributeMaxDynamicSharedMemorySize, attn_smem);
    cudaFuncSetAttribute(sgemm_qkv,  cudaFuncAttributeMaxDynamicSharedMemorySize, GEMM_SMEM_BYTES);
    cudaFuncSetAttribute(sgemm_proj, cudaFuncAttributeMaxDynamicSharedMemorySize, GEMM_SMEM_BYTES);

    conv_x<<<4096, 256>>>((const float4*)x, (uint2*)xh);
    conv_w<<<dim3(32, 32, 4), dim3(32, 8)>>>(Wq, Wk, Wv, Wo, wh);

    sgemm_qkv<<<dim3(8, 32, 3), 128, GEMM_SMEM_BYTES>>>(xh, wh, bq, bk, bv, qh, kh, vh);

    attn_kernel<<<dim3(64, N_HEADS), 128, attn_smem>>>(qh, kh, vh, ctxh);

    sgemm_proj<<<dim3(8, 32), 128, GEMM_SMEM_BYTES>>>(
        ctxh, wh + 3 * (size_t)D_DIM * D_DIM, bo, out);
}

// round 17
// speedup vs baseline: 1.1838x; 1.1838x over previous
#include <cuda_runtime.h>
#include <cuda_fp16.h>
#include <cuda_bf16.h>
#include <cstdint>

// ---------------------------------------------------------------------------
// SparseAttention: B=1, S=4096, D=1024, H=16, HD=64, BLOCK=128, C=32
// Round 16: round-14 structure + ldmatrix.x4 fragment loads everywhere
// (GEMM A/B frags, attn K/P frags; V already ldmatrix.trans).
// ---------------------------------------------------------------------------

#define S_LEN 4096
#define D_DIM 1024
#define N_HEADS 16
#define HEAD_DIM 64

__device__ __half g_qh[S_LEN * D_DIM];
__device__ __half g_kh[S_LEN * D_DIM];
__device__ __half g_vh[S_LEN * D_DIM];
__device__ __half g_ctxh[S_LEN * D_DIM];
__device__ __half g_xh[S_LEN * D_DIM];
__device__ __half g_wh[4 * D_DIM * D_DIM];   // W^T, [n][k], fp16

// ---------------------------------------------------------------------------
// helpers
// ---------------------------------------------------------------------------
__device__ __forceinline__ void mma_f16(float* c, const uint32_t* a, const uint32_t* b) {
    asm volatile(
        "mma.sync.aligned.m16n8k16.row.col.f32.f16.f16.f32 "
        "{%0,%1,%2,%3}, {%4,%5,%6,%7}, {%8,%9}, {%0,%1,%2,%3};"
        : "+f"(c[0]), "+f"(c[1]), "+f"(c[2]), "+f"(c[3])
        : "r"(a[0]), "r"(a[1]), "r"(a[2]), "r"(a[3]),
          "r"(b[0]), "r"(b[1]));
}

__device__ __forceinline__ void ldmx4(uint32_t& r0, uint32_t& r1,
                                      uint32_t& r2, uint32_t& r3, uint32_t saddr) {
    asm volatile(
        "ldmatrix.sync.aligned.m8n8.x4.shared.b16 {%0,%1,%2,%3}, [%4];"
        : "=r"(r0), "=r"(r1), "=r"(r2), "=r"(r3) : "r"(saddr));
}

__device__ __forceinline__ void ldmx4t(uint32_t& r0, uint32_t& r1,
                                       uint32_t& r2, uint32_t& r3, uint32_t saddr) {
    asm volatile(
        "ldmatrix.sync.aligned.m8n8.x4.trans.shared.b16 {%0,%1,%2,%3}, [%4];"
        : "=r"(r0), "=r"(r1), "=r"(r2), "=r"(r3) : "r"(saddr));
}

// Fast e^x for x <= ~7 (handles -1e30 -> ~0). Degree-4 2^f poly. No MUFU.
__device__ __forceinline__ float fexp(float x) {
    float y = fmaxf(x * 1.44269504089f, -125.0f);
    float z = y + 12582912.0f;
    float nf = z - 12582912.0f;
    float f = y - nf;
    float p = 9.6181291e-3f;
    p = fmaf(p, f, 5.5504109e-2f);
    p = fmaf(p, f, 2.4022651e-1f);
    p = fmaf(p, f, 6.9314718e-1f);
    p = fmaf(p, f, 1.0f);
    int n = __float_as_int(z) - 0x4B400000;
    return __int_as_float(__float_as_int(p) + (n << 23));
}

__device__ __forceinline__ void cp16h(__half* smem_dst, const __half* gmem_src) {
    uint32_t s = (uint32_t)__cvta_generic_to_shared(smem_dst);
    asm volatile("cp.async.cg.shared.global [%0], [%1], 16;\n" :: "r"(s), "l"(gmem_src));
}
#define CP_COMMIT() asm volatile("cp.async.commit_group;\n" ::: "memory")
#define CP_WAIT1()  asm volatile("cp.async.wait_group 1;\n" ::: "memory")
#define CP_WAIT0()  asm volatile("cp.async.wait_group 0;\n" ::: "memory")

// ---------------------------------------------------------------------------
// Conversions: x -> fp16; W[k][n] -> W^T[n][k] fp16
// ---------------------------------------------------------------------------
__global__ void conv_x(const float4* __restrict__ x, uint2* __restrict__ xh) {
    const int i = blockIdx.x * blockDim.x + threadIdx.x;
    float4 v = x[i];
    __half2 lo = __floats2half2_rn(v.x, v.y);
    __half2 hi = __floats2half2_rn(v.z, v.w);
    uint2 o;
    o.x = *(uint32_t*)&lo;
    o.y = *(uint32_t*)&hi;
    xh[i] = o;
}

__global__ void conv_w(
    const float* __restrict__ W0, const float* __restrict__ W1,
    const float* __restrict__ W2, const float* __restrict__ W3,
    __half* __restrict__ out)
{
    __shared__ float tile[32][33];
    const int z = blockIdx.z;
    const float* src = (z == 0) ? W0 : (z == 1) ? W1 : (z == 2) ? W2 : W3;
    __half* dst = out + (size_t)z * D_DIM * D_DIM;
    const int bx = blockIdx.x * 32, by = blockIdx.y * 32;
    const int tx = threadIdx.x, ty = threadIdx.y;
#pragma unroll
    for (int i = 0; i < 4; i++)
        tile[ty + 8 * i][tx] = src[(size_t)(by + ty + 8 * i) * D_DIM + bx + tx];
    __syncthreads();
#pragma unroll
    for (int i = 0; i < 4; i++)
        dst[(size_t)(bx + ty + 8 * i) * D_DIM + by + tx] =
            __float2half_rn(tile[tx][ty + 8 * i]);
}

// ---------------------------------------------------------------------------
// fp16 GEMM: C = (A @ B^T + bias) * scale; ldmatrix fragment loads.
// CTA 128x128, BK=32, 128 threads, warp tile 64x64, 3-stage pipeline.
// ---------------------------------------------------------------------------
#define HS 40
#define TILE_HG (128 * HS)
#define H_STAGE (2 * TILE_HG)
#define GEMM_SMEM_BYTES (3 * H_STAGE * 2)

__device__ __forceinline__ void gemm_load_tile_h(
    __half* As, __half* Bs, const __half* A, const __half* B,
    int m0, int n0, int k0, int tid)
{
#pragma unroll
    for (int rep = 0; rep < 4; rep++) {
        int idx = tid + 128 * rep;
        int row = idx >> 2;
        int c   = idx & 3;
        cp16h(As + row * HS + c * 8,
              A + (size_t)(m0 + row) * D_DIM + k0 + c * 8);
    }
#pragma unroll
    for (int rep = 0; rep < 4; rep++) {
        int idx = tid + 128 * rep;
        int row = idx >> 2;
        int c   = idx & 3;
        cp16h(Bs + row * HS + c * 8,
              B + (size_t)(n0 + row) * D_DIM + k0 + c * 8);
    }
}

template<int OUT_HALF>
__device__ __forceinline__ void gemm_body_h(
    const __half* __restrict__ A, const __half* __restrict__ B,
    const float* __restrict__ bias, void* __restrict__ Cout,
    float scale, __half* smh)
{
    __half* AsBuf[3] = { smh, smh + H_STAGE, smh + 2 * H_STAGE };
    __half* BsBuf[3] = { smh + TILE_HG, smh + H_STAGE + TILE_HG,
                         smh + 2 * H_STAGE + TILE_HG };

    const int tid = threadIdx.x;
    const int wid = tid >> 5;
    const int lane = tid & 31;
    const int g  = lane >> 2;
    const int t4 = lane & 3;
    const int warp_m = wid >> 1;
    const int warp_n = wid & 1;
    const int m0 = blockIdx.y * 128;
    const int n0 = blockIdx.x * 128;

    // ldmatrix per-lane row/col selectors
    const int a_row = (lane & 7) + ((lane >> 3) & 1) * 8;   // A: matrix row
    const int a_col = (lane >> 4) * 8;                      // A: k-half select
    const int b_row = (lane >> 4) * 8 + (lane & 7);         // B: within 2-ni group
    const int b_col = ((lane >> 3) & 1) * 8;                // B: k-half select

    float acc[4][8][4];
#pragma unroll
    for (int mi = 0; mi < 4; mi++)
#pragma unroll
        for (int ni = 0; ni < 8; ni++)
#pragma unroll
            for (int r = 0; r < 4; r++) acc[mi][ni][r] = 0.0f;

    const int niter = D_DIM / 32;

    gemm_load_tile_h(AsBuf[0], BsBuf[0], A, B, m0, n0, 0, tid);
    CP_COMMIT();
    gemm_load_tile_h(AsBuf[1], BsBuf[1], A, B, m0, n0, 32, tid);
    CP_COMMIT();

    for (int it = 0; it < niter; it++) {
        const int s = it % 3;
        if (it == niter - 1) { CP_WAIT0(); } else { CP_WAIT1(); }
        __syncthreads();
        if (it + 2 < niter) {
            gemm_load_tile_h(AsBuf[(it + 2) % 3], BsBuf[(it + 2) % 3],
                             A, B, m0, n0, (it + 2) * 32, tid);
            CP_COMMIT();
        }

        const __half* aBase = AsBuf[s] + (warp_m * 64) * HS;
        const __half* bBase = BsBuf[s] + (warp_n * 64) * HS;

#pragma unroll
        for (int step = 0; step < 2; step++) {
            const int kh0 = step * 16;
            uint32_t af[4][4];
#pragma unroll
            for (int mi = 0; mi < 4; mi++) {
                uint32_t sa = (uint32_t)__cvta_generic_to_shared(
                    aBase + (mi * 16 + a_row) * HS + kh0 + a_col);
                ldmx4(af[mi][0], af[mi][1], af[mi][2], af[mi][3], sa);
            }
            uint32_t bf[8][2];
#pragma unroll
            for (int j = 0; j < 4; j++) {
                uint32_t sb = (uint32_t)__cvta_generic_to_shared(
                    bBase + (j * 16 + b_row) * HS + kh0 + b_col);
                ldmx4(bf[2 * j][0], bf[2 * j][1],
                      bf[2 * j + 1][0], bf[2 * j + 1][1], sb);
            }
#pragma unroll
            for (int mi = 0; mi < 4; mi++)
#pragma unroll
                for (int ni = 0; ni < 8; ni++)
                    mma_f16(acc[mi][ni], af[mi], bf[ni]);
        }
    }

#pragma unroll
    for (int mi = 0; mi < 4; mi++) {
        int row = m0 + warp_m * 64 + mi * 16 + g;
#pragma unroll
        for (int ni = 0; ni < 8; ni++) {
            int col = n0 + warp_n * 64 + ni * 8 + 2 * t4;
            float b0 = bias[col], b1 = bias[col + 1];
            float o0 = (acc[mi][ni][0] + b0) * scale;
            float o1 = (acc[mi][ni][1] + b1) * scale;
            float o2 = (acc[mi][ni][2] + b0) * scale;
            float o3 = (acc[mi][ni][3] + b1) * scale;
            if (OUT_HALF) {
                __half* C = (__half*)Cout;
                __half2 h0 = __floats2half2_rn(o0, o1);
                __half2 h1 = __floats2half2_rn(o2, o3);
                *(__half2*)(C + (size_t)row * D_DIM + col)       = h0;
                *(__half2*)(C + (size_t)(row + 8) * D_DIM + col) = h1;
            } else {
                float* C = (float*)Cout;
                C[(size_t)row * D_DIM + col]           = o0;
                C[(size_t)row * D_DIM + col + 1]       = o1;
                C[(size_t)(row + 8) * D_DIM + col]     = o2;
                C[(size_t)(row + 8) * D_DIM + col + 1] = o3;
            }
        }
    }
}

__global__ __launch_bounds__(128, 2) void sgemm_qkv(
    const __half* __restrict__ xh, const __half* __restrict__ wh,
    const float* __restrict__ bq, const float* __restrict__ bk,
    const float* __restrict__ bv,
    __half* __restrict__ q, __half* __restrict__ k, __half* __restrict__ v)
{
    extern __shared__ __half smh[];
    const int z = blockIdx.z;
    const __half* W = wh + (size_t)z * D_DIM * D_DIM;
    const float* b = (z == 0) ? bq : (z == 1) ? bk : bv;
    __half* C      = (z == 0) ? q  : (z == 1) ? k  : v;
    const float sc = (z == 0) ? 0.125f : 1.0f;
    gemm_body_h<1>(xh, W, b, C, sc, smh);
}

__global__ __launch_bounds__(128, 2) void sgemm_proj(
    const __half* __restrict__ A, const __half* __restrict__ B,
    const float* __restrict__ bias, float* __restrict__ C)
{
    extern __shared__ __half smh[];
    gemm_body_h<0>(A, B, bias, C, 1.0f, smh);
}

// ---------------------------------------------------------------------------
// Sparse flash attention (round-14 structure): 128 q-rows, 256 threads,
// 64-key tiles, 2 CTAs/SM; K/P frags via ldmatrix.x4, V via ldmatrix.trans.
// ---------------------------------------------------------------------------
__device__ __forceinline__ int gather_key(int gk) {
    int j = gk / 33;
    int r = gk - j * 33;
    return j * 128 + (r == 0 ? 0 : 95 + r);
}

#define TSH 72                       // halves per tile row (64 + 8 pad)
#define T_TILE_H (64 * TSH)
#define ATTN_SMEM_HALVES (4 * T_TILE_H + 128 * TSH)
#define BIG_NEG (-1e30f)

__global__ __launch_bounds__(256, 2) void attn_kernel(
    const __half* __restrict__ Q, const __half* __restrict__ K,
    const __half* __restrict__ V, __half* __restrict__ ctxh)
{
    extern __shared__ __half smh[];
    __half* KsBuf[2] = { smh, smh + T_TILE_H };
    __half* VsBuf[2] = { smh + 2 * T_TILE_H, smh + 3 * T_TILE_H };
    __half* Ps = smh + 4 * T_TILE_H;   // [128][72]

    const int qb = 31 - blockIdx.x;
    const int h  = blockIdx.y;
    const int tid = threadIdx.x;
    const int wid = tid >> 5;
    const int lane = tid & 31;
    const int g  = lane >> 2;
    const int t4 = lane & 3;

    const int nG = 33 * qb;
    const int nT = (nG + 63) >> 6;
    const int nTot = nT + 2;
    const int key_lane = tid >> 2;     // 0..63
    const int c4b      = tid & 3;

    // ldmatrix lane selectors
    const int a_row = (lane & 7) + ((lane >> 3) & 1) * 8;
    const int a_col = (lane >> 4) * 8;
    const int b_row = (lane >> 4) * 8 + (lane & 7);
    const int b_col = ((lane >> 3) & 1) * 8;

    // ---- Q fragments fp16 (loaded once from gmem) ----
    const __half* Qb = Q + (size_t)(qb * 128 + wid * 16) * D_DIM + h * HEAD_DIM;
    uint32_t qa[4][4];
#pragma unroll
    for (int ks = 0; ks < 4; ks++) {
        int kh = ks * 16 + 2 * t4;
        qa[ks][0] = *(const uint32_t*)(Qb + (size_t)(g)     * D_DIM + kh);
        qa[ks][1] = *(const uint32_t*)(Qb + (size_t)(g + 8) * D_DIM + kh);
        qa[ks][2] = *(const uint32_t*)(Qb + (size_t)(g)     * D_DIM + kh + 8);
        qa[ks][3] = *(const uint32_t*)(Qb + (size_t)(g + 8) * D_DIM + kh + 8);
    }

    auto load_tile = [&](int t, int buf) {
        int gk;
        if (t >= nT) gk = qb * 128 + (t - nT) * 64 + key_lane;
        else {
            int gg = t * 64 + key_lane;
            gk = (gg < nG) ? gather_key(gg) : 0;
        }
        const __half* Krow = K + (size_t)gk * D_DIM + h * HEAD_DIM;
        const __half* Vrow = V + (size_t)gk * D_DIM + h * HEAD_DIM;
        __half* kd = KsBuf[buf] + key_lane * TSH;
        __half* vd = VsBuf[buf] + key_lane * TSH;
#pragma unroll
        for (int rep = 0; rep < 2; rep++) {
            int c = c4b + 4 * rep;
            cp16h(kd + c * 8, Krow + c * 8);
            cp16h(vd + c * 8, Vrow + c * 8);
        }
    };

    float lrow[2] = { 0.0f, 0.0f };
    float Oacc[8][4];
#pragma unroll
    for (int ni = 0; ni < 8; ni++)
#pragma unroll
        for (int r = 0; r < 4; r++) Oacc[ni][r] = 0.0f;

    load_tile(0, 0);
    CP_COMMIT();

    for (int t = 0; t < nTot; t++) {
        CP_WAIT0();
        __syncthreads();
        if (t + 1 < nTot) {
            load_tile(t + 1, (t + 1) & 1);
            CP_COMMIT();
        }
        const __half* Kb = KsBuf[t & 1];
        const __half* Vb = VsBuf[t & 1];

        // ---- S = Q K^T (K B-frags via ldmatrix.x4) ----
        float sacc[8][4];
#pragma unroll
        for (int ni = 0; ni < 8; ni++)
#pragma unroll
            for (int r = 0; r < 4; r++) sacc[ni][r] = 0.0f;

#pragma unroll
        for (int ks = 0; ks < 4; ks++) {
            const int kh0 = ks * 16;
            uint32_t bf[8][2];
#pragma unroll
            for (int j = 0; j < 4; j++) {
                uint32_t sb = (uint32_t)__cvta_generic_to_shared(
                    Kb + (j * 16 + b_row) * TSH + kh0 + b_col);
                ldmx4(bf[2 * j][0], bf[2 * j][1],
                      bf[2 * j + 1][0], bf[2 * j + 1][1], sb);
            }
#pragma unroll
            for (int ni = 0; ni < 8; ni++)
                mma_f16(sacc[ni], qa[ks], bf[ni]);
        }

        // ---- mask (only when needed) ----
        const int r0 = wid * 16 + g;
        const int r1 = r0 + 8;
        if (t >= nT) {
            const int cb = (t - nT) * 64;
#pragma unroll
            for (int ni = 0; ni < 8; ni++) {
                int c0 = cb + ni * 8 + 2 * t4;
                if (c0     > r0) sacc[ni][0] = BIG_NEG;
                if (c0 + 1 > r0) sacc[ni][1] = BIG_NEG;
                if (c0     > r1) sacc[ni][2] = BIG_NEG;
                if (c0 + 1 > r1) sacc[ni][3] = BIG_NEG;
            }
        } else if (t * 64 + 64 > nG) {
            const int base = t * 64;
#pragma unroll
            for (int ni = 0; ni < 8; ni++) {
                int c0 = base + ni * 8 + 2 * t4;
                if (c0     >= nG) { sacc[ni][0] = BIG_NEG; sacc[ni][2] = BIG_NEG; }
                if (c0 + 1 >= nG) { sacc[ni][1] = BIG_NEG; sacc[ni][3] = BIG_NEG; }
            }
        }

        // ---- p = exp(s), partial l, store P fp16 ----
#pragma unroll
        for (int ni = 0; ni < 8; ni++) {
            float p0 = fexp(sacc[ni][0]);
            float p1 = fexp(sacc[ni][1]);
            float p2 = fexp(sacc[ni][2]);
            float p3 = fexp(sacc[ni][3]);
            lrow[0] += p0 + p1;
            lrow[1] += p2 + p3;
            int c = ni * 8 + 2 * t4;
            __half2 w0 = __floats2half2_rn(p0, p1);
            __half2 w1 = __floats2half2_rn(p2, p3);
            *(__half2*)(Ps + r0 * TSH + c) = w0;
            *(__half2*)(Ps + r1 * TSH + c) = w1;
        }
        __syncwarp();

        // ---- O += P @ V (P A-frags via ldmatrix.x4, V via ldmatrix.trans) ----
        const __half* pB = Ps + (wid * 16) * TSH;
#pragma unroll
        for (int ks = 0; ks < 4; ks++) {
            const int kh0 = ks * 16;
            uint32_t a[4];
            {
                uint32_t sa = (uint32_t)__cvta_generic_to_shared(
                    pB + a_row * TSH + kh0 + a_col);
                ldmx4(a[0], a[1], a[2], a[3], sa);
            }
            uint32_t bf[8][2];
#pragma unroll
            for (int np = 0; np < 4; np++) {
                int m = lane >> 3;
                int key = ks * 16 + (lane & 7) + 8 * (m & 1);
                int dcol = (2 * np + (m >> 1)) * 8;
                uint32_t saddr = (uint32_t)__cvta_generic_to_shared(
                    Vb + key * TSH + dcol);
                ldmx4t(bf[2 * np][0], bf[2 * np][1],
                       bf[2 * np + 1][0], bf[2 * np + 1][1], saddr);
            }
#pragma unroll
            for (int ni = 0; ni < 8; ni++)
                mma_f16(Oacc[ni], a, bf[ni]);
        }
    }

    // ---- final l reduction, epilogue (ctx fp16) ----
    lrow[0] += __shfl_xor_sync(0xffffffffu, lrow[0], 1);
    lrow[0] += __shfl_xor_sync(0xffffffffu, lrow[0], 2);
    lrow[1] += __shfl_xor_sync(0xffffffffu, lrow[1], 1);
    lrow[1] += __shfl_xor_sync(0xffffffffu, lrow[1], 2);

    const float inv0 = 1.0f / lrow[0];
    const float inv1 = 1.0f / lrow[1];
    const int gr0 = qb * 128 + wid * 16 + g;
    const int gr1 = gr0 + 8;
#pragma unroll
    for (int ni = 0; ni < 8; ni++) {
        int c = h * HEAD_DIM + ni * 8 + 2 * t4;
        __half2 h0 = __floats2half2_rn(Oacc[ni][0] * inv0, Oacc[ni][1] * inv0);
        __half2 h1 = __floats2half2_rn(Oacc[ni][2] * inv1, Oacc[ni][3] * inv1);
        *(__half2*)(ctxh + (size_t)gr0 * D_DIM + c) = h0;
        *(__half2*)(ctxh + (size_t)gr1 * D_DIM + c) = h1;
    }
}

// ---------------------------------------------------------------------------
extern "C" void kernel_launch(void* const* d_in, const int* in_sizes, int n_in,
                              void* d_out, int out_size)
{
    const float* x  = (const float*)d_in[0];
    const float* Wq = (const float*)d_in[1];
    const float* bq = (const float*)d_in[2];
    const float* Wk = (const float*)d_in[3];
    const float* bk = (const float*)d_in[4];
    const float* Wv = (const float*)d_in[5];
    const float* bv = (const float*)d_in[6];
    const float* Wo = (const float*)d_in[7];
    const float* bo = (const float*)d_in[8];
    float* out = (float*)d_out;

    __half *qh, *kh, *vh, *ctxh, *xh, *wh;
    cudaGetSymbolAddress((void**)&qh,   g_qh);
    cudaGetSymbolAddress((void**)&kh,   g_kh);
    cudaGetSymbolAddress((void**)&vh,   g_vh);
    cudaGetSymbolAddress((void**)&ctxh, g_ctxh);
    cudaGetSymbolAddress((void**)&xh,   g_xh);
    cudaGetSymbolAddress((void**)&wh,   g_wh);

    const int attn_smem = ATTN_SMEM_HALVES * 2;
    cudaFuncSetAttribute(attn_kernel, cudaFuncAttributeMaxDynamicSharedMemorySize, attn_smem);
    cudaFuncSetAttribute(sgemm_qkv,  cudaFuncAttributeMaxDynamicSharedMemorySize, GEMM_SMEM_BYTES);
    cudaFuncSetAttribute(sgemm_proj, cudaFuncAttributeMaxDynamicSharedMemorySize, GEMM_SMEM_BYTES);

    conv_x<<<4096, 256>>>((const float4*)x, (uint2*)xh);
    conv_w<<<dim3(32, 32, 4), dim3(32, 8)>>>(Wq, Wk, Wv, Wo, wh);

    sgemm_qkv<<<dim3(8, 32, 3), 128, GEMM_SMEM_BYTES>>>(xh, wh, bq, bk, bv, qh, kh, vh);

    attn_kernel<<<dim3(32, N_HEADS), 256, attn_smem>>>(qh, kh, vh, ctxh);

    sgemm_proj<<<dim3(8, 32), 128, GEMM_SMEM_BYTES>>>(
        ctxh, wh + 3 * (size_t)D_DIM * D_DIM, bo, out);
}